// round 3
// baseline (speedup 1.0000x reference)
#include <cuda_runtime.h>

// Problem constants (fixed by setup_inputs)
#define BB 2
#define NN 16384
#define MM 4096
#define CC 32
#define KK 32

// radius*radius as float: float(0.01)
#define R2 0.00999999977648258209228515625f

// Scratch for ball-query indices: [B][M][K]
__device__ int g_idx[BB * MM * KK];

// ---------------------------------------------------------------------------
// Kernel 1: ball query. One warp per center. Scan points in 32-wide chunks,
// compact valid indices in ascending order via ballot, early-exit when K found
// (warp-coherent: cnt is uniform across the warp).
//
// Arithmetic model of the XLA lowering:
//   p2, c2: separate multiply HLO + reduce(add) -> (x*x + y*y) + z*z, NO fma
//   cp:     einsum -> batched GEMM k-loop      -> fma(z, fma(y, x*x)) chain
//   d2:     sub(add(c2,p2), 2*cp); 2*cp exact so rounding is unambiguous
// ---------------------------------------------------------------------------
__global__ __launch_bounds__(256) void ball_query_kernel(
    const float* __restrict__ pts,   // [B][3][N]
    const float* __restrict__ ctr)   // [B][3][M]
{
    __shared__ int sidx[8][KK];

    const int warp = threadIdx.x >> 5;
    const int lane = threadIdx.x & 31;
    const int gw = blockIdx.x * 8 + warp;
    if (gw >= BB * MM) return;
    const int b = gw / MM;
    const int m = gw - b * MM;

    const float* __restrict__ P = pts + b * 3 * NN;
    const float cx = ctr[(b * 3 + 0) * MM + m];
    const float cy = ctr[(b * 3 + 1) * MM + m];
    const float cz = ctr[(b * 3 + 2) * MM + m];
    // c2 = (cx*cx + cy*cy) + cz*cz  -- plain mul/add reduce, no contraction
    const float c2 = __fadd_rn(__fadd_rn(__fmul_rn(cx, cx), __fmul_rn(cy, cy)),
                               __fmul_rn(cz, cz));

    int cnt = 0;
    for (int base = 0; base < NN; base += 32) {
        const int i = base + lane;
        const float px = P[i];
        const float py = P[NN + i];
        const float pz = P[2 * NN + i];
        // p2: plain mul/add reduce (no fma)
        const float p2 = __fadd_rn(__fadd_rn(__fmul_rn(px, px), __fmul_rn(py, py)),
                                   __fmul_rn(pz, pz));
        // dot: GEMM-style fma chain
        const float dot = __fmaf_rn(cz, pz, __fmaf_rn(cy, py, __fmul_rn(cx, px)));
        // d2 = (c2 + p2) - 2*dot ; 2*dot exact -> single unambiguous rounding
        const float d2 = __fadd_rn(__fadd_rn(c2, p2), __fmul_rn(-2.0f, dot));
        const bool valid = d2 < R2;
        const unsigned mask = __ballot_sync(0xffffffffu, valid);
        if (valid) {
            const int pos = cnt + __popc(mask & ((1u << lane) - 1u));
            if (pos < KK) sidx[warp][pos] = i;
        }
        cnt += __popc(mask);
        if (cnt >= KK) break;
    }
    __syncwarp();

    int v;
    if (cnt == 0) {
        v = 0;                                   // no neighbor: index 0
    } else {
        const int first = sidx[warp][0];
        v = (lane < cnt && lane < KK) ? sidx[warp][lane] : first;
    }
    g_idx[(b * MM + m) * KK + lane] = v;
}

// ---------------------------------------------------------------------------
// Kernel 2: grouping. grid = (M/128, 35 channels, B). 128 threads, one m each.
// Stage the idx tile in padded smem (stride 33 -> conflict free), then for
// each k gather one value per thread and store coalesced over m.
// out[b][c][k][m]:
//   c <  3 : points_coords[b][c][idx] - centers[b][c][m]
//   c >= 3 : points_features[b][c-3][idx]
// ---------------------------------------------------------------------------
__global__ __launch_bounds__(128) void group_kernel(
    const float* __restrict__ pts,    // [B][3][N]
    const float* __restrict__ ctr,    // [B][3][M]
    const float* __restrict__ feat,   // [B][C][N]
    float* __restrict__ out)          // [B][35][K][M]
{
    __shared__ int sidx[128 * 33];

    const int tid = threadIdx.x;
    const int m0 = blockIdx.x * 128;
    const int c  = blockIdx.y;
    const int b  = blockIdx.z;

    // Load idx tile coalesced: scratch layout [b][m][k]
    const int* __restrict__ gbase = g_idx + (b * MM + m0) * KK;
    #pragma unroll
    for (int t = tid; t < 128 * KK; t += 128) {
        const int ml = t >> 5;
        const int k = t & 31;
        sidx[ml * 33 + k] = gbase[t];
    }
    __syncthreads();

    const float* __restrict__ src;
    float sub = 0.0f;
    if (c < 3) {
        src = pts + (b * 3 + c) * NN;
        sub = ctr[(b * 3 + c) * MM + m0 + tid];
    } else {
        src = feat + (b * CC + (c - 3)) * NN;
    }

    float* __restrict__ o = out + (size_t)((b * 35 + c) * KK) * MM + m0 + tid;
    const int* __restrict__ myidx = &sidx[tid * 33];

    #pragma unroll
    for (int k = 0; k < KK; ++k) {
        const int idx = myidx[k];
        const float v = __fadd_rn(__ldg(src + idx), -sub);
        o[(size_t)k * MM] = v;
    }
}

extern "C" void kernel_launch(void* const* d_in, const int* in_sizes, int n_in,
                              void* d_out, int out_size)
{
    const float* pts  = (const float*)d_in[0];   // points_coords  [B][3][N]
    const float* ctr  = (const float*)d_in[1];   // centers_coords [B][3][M]
    const float* feat = (const float*)d_in[2];   // points_features[B][C][N]
    float* out = (float*)d_out;

    // Kernel 1: 8192 warps, 8 warps/block -> 1024 blocks
    ball_query_kernel<<<(BB * MM + 7) / 8, 256>>>(pts, ctr);

    // Kernel 2: (M/128, 35, B) = (32, 35, 2) blocks of 128 threads
    dim3 grid(MM / 128, 35, BB);
    group_kernel<<<grid, 128>>>(pts, ctr, feat, out);
}

// round 4
// speedup vs baseline: 1.1423x; 1.1423x over previous
#include <cuda_runtime.h>

#define BB 2
#define NN 16384
#define MM 4096
#define CC 32
#define KK 32

// float(0.01)
#define R2 0.00999999977648258209228515625f

// Scratch: ball-query indices [B][M][K], transposed features [B][N][C]
__device__ int   g_idx[BB * MM * KK];
__device__ float g_feat_t[BB * NN * CC];

#define BQ_WARPS 16
#define TILE_PTS 2048

// ---------------------------------------------------------------------------
// Kernel 1: ball query, CTA-tiled. 16 warps/block, one center per warp.
// Points staged in smem (x,y,z,p2) in tiles of 2048; every warp scans the
// shared tile -> 16x less L2 traffic. Per-warp early exit; block exits when
// all warps done (__syncthreads_and).
// Arithmetic bit-matches the XLA lowering (DO NOT CHANGE):
//   p2,c2: (x*x + y*y) + z*z  plain mul/add
//   dot:   fma(cz,pz, fma(cy,py, cx*px))
//   d2:    (c2 + p2) - 2*dot
// ---------------------------------------------------------------------------
__global__ __launch_bounds__(512) void ball_query_kernel(
    const float* __restrict__ pts,   // [B][3][N]
    const float* __restrict__ ctr)   // [B][3][M]
{
    __shared__ float sx[TILE_PTS], sy[TILE_PTS], sz[TILE_PTS], sw[TILE_PTS];
    __shared__ int sidx[BQ_WARPS][KK];

    const int warp = threadIdx.x >> 5;
    const int lane = threadIdx.x & 31;
    const int gw = blockIdx.x * BQ_WARPS + warp;     // 512 blocks * 16 warps
    const int b = gw / MM;                           // blocks never straddle b
    const int m = gw & (MM - 1);

    const float cx = ctr[(b * 3 + 0) * MM + m];
    const float cy = ctr[(b * 3 + 1) * MM + m];
    const float cz = ctr[(b * 3 + 2) * MM + m];
    const float c2 = __fadd_rn(__fadd_rn(__fmul_rn(cx, cx), __fmul_rn(cy, cy)),
                               __fmul_rn(cz, cz));

    const float* __restrict__ P = pts + b * 3 * NN;

    int cnt = 0;
    bool mydone = false;

    for (int t0 = 0; t0 < NN; t0 += TILE_PTS) {
        // Cooperative tile load + p2 precompute (exact reference rounding)
        for (int i = threadIdx.x; i < TILE_PTS; i += 512) {
            const float x = P[t0 + i];
            const float y = P[NN + t0 + i];
            const float z = P[2 * NN + t0 + i];
            sx[i] = x; sy[i] = y; sz[i] = z;
            sw[i] = __fadd_rn(__fadd_rn(__fmul_rn(x, x), __fmul_rn(y, y)),
                              __fmul_rn(z, z));
        }
        __syncthreads();

        if (!mydone) {
            for (int base = 0; base < TILE_PTS; base += 32) {
                const int li = base + lane;
                const float px = sx[li];
                const float py = sy[li];
                const float pz = sz[li];
                const float p2 = sw[li];
                const float dot = __fmaf_rn(cz, pz, __fmaf_rn(cy, py, __fmul_rn(cx, px)));
                const float d2 = __fadd_rn(__fadd_rn(c2, p2), __fmul_rn(-2.0f, dot));
                const bool valid = d2 < R2;
                const unsigned mask = __ballot_sync(0xffffffffu, valid);
                if (valid) {
                    const int pos = cnt + __popc(mask & ((1u << lane) - 1u));
                    if (pos < KK) sidx[warp][pos] = t0 + li;
                }
                cnt += __popc(mask);
                if (cnt >= KK) break;
            }
            if (cnt >= KK) mydone = true;
        }
        // Barrier (protects tile reuse) + collective exit
        if (__syncthreads_and(mydone ? 1 : 0)) break;
    }
    __syncwarp();

    int v;
    if (cnt == 0) {
        v = 0;
    } else {
        const int first = sidx[warp][0];
        v = (lane < cnt && lane < KK) ? sidx[warp][lane] : first;
    }
    g_idx[(b * MM + m) * KK + lane] = v;
}

// ---------------------------------------------------------------------------
// Kernel 2: transpose features [B][C][N] -> [B][N][C]  (128B rows for gather)
// ---------------------------------------------------------------------------
__global__ __launch_bounds__(256) void transpose_feat_kernel(
    const float* __restrict__ feat)   // [B][C][N]
{
    __shared__ float sm[32][33];
    const int n0 = blockIdx.x * 32;
    const int b  = blockIdx.y;
    const int tx = threadIdx.x;       // 32
    const int ty = threadIdx.y;       // 8

    #pragma unroll
    for (int i = ty; i < 32; i += 8)
        sm[i][tx] = feat[(b * CC + i) * NN + n0 + tx];
    __syncthreads();
    #pragma unroll
    for (int i = ty; i < 32; i += 8)
        g_feat_t[(size_t)(b * NN + n0 + i) * CC + tx] = sm[tx][i];
}

// ---------------------------------------------------------------------------
// Kernel 3: coords grouping (channels 0..2). 128 threads, one m each.
// Register-array batching for MLP=32.
// ---------------------------------------------------------------------------
__global__ __launch_bounds__(128) void group_coords_kernel(
    const float* __restrict__ pts,    // [B][3][N]
    const float* __restrict__ ctr,    // [B][3][M]
    float* __restrict__ out)          // [B][35][K][M]
{
    __shared__ int sidx[128 * 33];

    const int tid = threadIdx.x;
    const int m0 = blockIdx.x * 128;
    const int c  = blockIdx.y;        // 0..2
    const int b  = blockIdx.z;

    const int* __restrict__ gbase = g_idx + (b * MM + m0) * KK;
    #pragma unroll
    for (int t = tid; t < 128 * KK; t += 128) {
        sidx[(t >> 5) * 33 + (t & 31)] = gbase[t];
    }
    __syncthreads();

    const float* __restrict__ src = pts + (b * 3 + c) * NN;
    const float sub = ctr[(b * 3 + c) * MM + m0 + tid];
    float* __restrict__ o = out + (size_t)((b * 35 + c) * KK) * MM + m0 + tid;
    const int* __restrict__ myidx = &sidx[tid * 33];

    float vals[KK];
    #pragma unroll
    for (int k = 0; k < KK; ++k) vals[k] = __ldg(src + myidx[k]);
    #pragma unroll
    for (int k = 0; k < KK; ++k) o[(size_t)k * MM] = __fadd_rn(vals[k], -sub);
}

// ---------------------------------------------------------------------------
// Kernel 4: feature grouping via transposed gather.
// Block: 256 thr (8 warps), m-tile = 32, all k, all 32 feat channels.
// Warp w owns k = kc*8 + w; for each m it gathers the full 32-channel row
// feat_t[idx] in ONE coalesced 128B load (lane = channel), stages into a
// padded smem tile [c][k8][m] (stride 257 -> conflict-free), then the block
// writes out coalesced over m.
// ---------------------------------------------------------------------------
__global__ __launch_bounds__(256) void group_feat_kernel(
    float* __restrict__ out)          // [B][35][K][M]
{
    __shared__ int   sidx[32 * KK];         // [m][k]
    __shared__ float tile[32 * 257];        // [c][k8*32+m], padded stride

    const int tid  = threadIdx.x;
    const int w    = tid >> 5;              // 0..7
    const int lane = tid & 31;
    const int m0 = blockIdx.x * 32;
    const int b  = blockIdx.y;

    const int* __restrict__ gbase = g_idx + (b * MM + m0) * KK;
    #pragma unroll
    for (int t = tid; t < 32 * KK; t += 256) sidx[t] = gbase[t];
    __syncthreads();

    const float* __restrict__ ft = g_feat_t + (size_t)b * NN * CC;

    for (int kc = 0; kc < 4; ++kc) {
        const int k = kc * 8 + w;
        // Gather: 32 (m) rows of 32 channels each, 128B coalesced
        #pragma unroll
        for (int m = 0; m < 32; ++m) {
            const int idx = sidx[m * KK + k];                 // broadcast LDS
            const float v = __ldg(ft + (size_t)idx * CC + lane);
            tile[lane * 257 + w * 32 + m] = v;                // conflict-free
        }
        __syncthreads();
        // Write out: iter i = channel c; warp w = k-offset; lane = m
        #pragma unroll
        for (int i = 0; i < 32; ++i) {
            const float v = tile[i * 257 + w * 32 + lane];
            out[(size_t)((b * 35 + 3 + i) * KK + kc * 8 + w) * MM + m0 + lane] = v;
        }
        __syncthreads();
    }
}

extern "C" void kernel_launch(void* const* d_in, const int* in_sizes, int n_in,
                              void* d_out, int out_size)
{
    const float* pts  = (const float*)d_in[0];   // [B][3][N]
    const float* ctr  = (const float*)d_in[1];   // [B][3][M]
    const float* feat = (const float*)d_in[2];   // [B][C][N]
    float* out = (float*)d_out;

    // transpose (independent) then ball query
    {
        dim3 grid(NN / 32, BB);
        dim3 block(32, 8);
        transpose_feat_kernel<<<grid, block>>>(feat);
    }
    ball_query_kernel<<<BB * MM / BQ_WARPS, 512>>>(pts, ctr);

    {
        dim3 grid(MM / 128, 3, BB);
        group_coords_kernel<<<grid, 128>>>(pts, ctr, out);
    }
    {
        dim3 grid(MM / 32, BB);
        group_feat_kernel<<<grid, 256>>>(out);
    }
}

// round 5
// speedup vs baseline: 3.0571x; 2.6762x over previous
#include <cuda_runtime.h>

#define BB 2
#define NN 16384
#define MM 4096
#define CC 32
#define KK 32

// float(0.01) — comparison threshold, frozen (bit-matches reference)
#define R2 0.00999999977648258209228515625f

#define GD 10
#define NCELL 1000
#define CAP 256

// Scratch
__device__ int    g_idx[BB * MM * KK];        // ball-query result [B][M][K]
__device__ float  g_feat_t[BB * NN * CC];     // transposed features [B][N][C]
__device__ float4 g_pts4[BB * NN];            // cell-sorted (x,y,z,idx-bits)
__device__ int    g_cellcur[BB * NCELL];      // counts -> scatter cursors
__device__ int    g_cellstart[BB * (NCELL + 1)];

// ---------------------------------------------------------------------------
__device__ __forceinline__ int cell_of(float x, float y, float z) {
    int cx = (int)(x * 10.f); cx = cx < 0 ? 0 : (cx > 9 ? 9 : cx);
    int cy = (int)(y * 10.f); cy = cy < 0 ? 0 : (cy > 9 ? 9 : cy);
    int cz = (int)(z * 10.f); cz = cz < 0 ? 0 : (cz > 9 ? 9 : cz);
    return (cx * GD + cy) * GD + cz;
}

__global__ void zero_cells_kernel() {
    int i = blockIdx.x * blockDim.x + threadIdx.x;
    if (i < BB * NCELL) g_cellcur[i] = 0;
}

__global__ void count_kernel(const float* __restrict__ pts) {
    int i = blockIdx.x * blockDim.x + threadIdx.x;
    if (i >= BB * NN) return;
    const int b = i / NN, n = i - b * NN;
    const float* __restrict__ P = pts + b * 3 * NN;
    atomicAdd(&g_cellcur[b * NCELL + cell_of(P[n], P[NN + n], P[2 * NN + n])], 1);
}

// grid = BB blocks, 1024 threads: exclusive scan of 1000 counts per batch
__global__ __launch_bounds__(1024) void prefix_kernel() {
    __shared__ int s[1024];
    const int b = blockIdx.x, tid = threadIdx.x;
    const int v = (tid < NCELL) ? g_cellcur[b * NCELL + tid] : 0;
    s[tid] = v;
    __syncthreads();
    #pragma unroll
    for (int off = 1; off < 1024; off <<= 1) {
        const int t = (tid >= off) ? s[tid - off] : 0;
        __syncthreads();
        s[tid] += t;
        __syncthreads();
    }
    const int excl = s[tid] - v;
    if (tid < NCELL) {
        g_cellstart[b * (NCELL + 1) + tid] = excl;
        g_cellcur[b * NCELL + tid] = excl;       // scatter cursor
    }
    if (tid == NCELL - 1) g_cellstart[b * (NCELL + 1) + NCELL] = s[tid];
}

__global__ void scatter_kernel(const float* __restrict__ pts) {
    int i = blockIdx.x * blockDim.x + threadIdx.x;
    if (i >= BB * NN) return;
    const int b = i / NN, n = i - b * NN;
    const float* __restrict__ P = pts + b * 3 * NN;
    const float x = P[n], y = P[NN + n], z = P[2 * NN + n];
    const int pos = atomicAdd(&g_cellcur[b * NCELL + cell_of(x, y, z)], 1);
    g_pts4[b * NN + pos] = make_float4(x, y, z, __int_as_float(n));
}

// ---------------------------------------------------------------------------
// Query: warp per center. Scan 27-neighborhood candidates (cell-sorted),
// collect valid ORIGINAL indices into buf, then rank-select 32 smallest.
// Arithmetic bit-matches XLA lowering (FROZEN):
//   p2,c2: (x*x + y*y) + z*z  plain mul/add
//   dot:   fma(cz,pz, fma(cy,py, cx*px))
//   d2:    (c2 + p2) - 2*dot
// ---------------------------------------------------------------------------
#define QW 8
__global__ __launch_bounds__(256) void query_kernel(const float* __restrict__ ctr)
{
    __shared__ int buf[QW][CAP];
    __shared__ int sidx[QW][KK];

    const int w = threadIdx.x >> 5;
    const int lane = threadIdx.x & 31;
    const int gw = blockIdx.x * QW + w;           // 1024 blocks * 8 warps
    const int b = gw >> 12;                       // / MM
    const int m = gw & (MM - 1);

    const float cx = ctr[(b * 3 + 0) * MM + m];
    const float cy = ctr[(b * 3 + 1) * MM + m];
    const float cz = ctr[(b * 3 + 2) * MM + m];
    const float c2 = __fadd_rn(__fadd_rn(__fmul_rn(cx, cx), __fmul_rn(cy, cy)),
                               __fmul_rn(cz, cz));

    // conservative cell range (1e-4 margin swamps fp rounding)
    int lox = (int)((cx - 0.1001f) * 10.f); lox = lox < 0 ? 0 : lox;
    int hix = (int)((cx + 0.1001f) * 10.f); hix = hix > 9 ? 9 : hix;
    int loy = (int)((cy - 0.1001f) * 10.f); loy = loy < 0 ? 0 : loy;
    int hiy = (int)((cy + 0.1001f) * 10.f); hiy = hiy > 9 ? 9 : hiy;
    int loz = (int)((cz - 0.1001f) * 10.f); loz = loz < 0 ? 0 : loz;
    int hiz = (int)((cz + 0.1001f) * 10.f); hiz = hiz > 9 ? 9 : hiz;

    const int* __restrict__ cs = g_cellstart + b * (NCELL + 1);
    const float4* __restrict__ pp = g_pts4 + b * NN;

    int cnt = 0;
    for (int xi = lox; xi <= hix; ++xi) {
        for (int yi = loy; yi <= hiy; ++yi) {
            const int base = (xi * GD + yi) * GD;
            const int s = cs[base + loz];
            const int e = cs[base + hiz + 1];
            for (int t = s + lane; t - lane < e; t += 32) {
                const bool inb = t < e;
                float4 q;
                if (inb) q = pp[t];
                else     q = make_float4(1e9f, 1e9f, 1e9f, 0.f);
                const float p2 = __fadd_rn(__fadd_rn(__fmul_rn(q.x, q.x), __fmul_rn(q.y, q.y)),
                                           __fmul_rn(q.z, q.z));
                const float dot = __fmaf_rn(cz, q.z, __fmaf_rn(cy, q.y, __fmul_rn(cx, q.x)));
                const float d2 = __fadd_rn(__fadd_rn(c2, p2), __fmul_rn(-2.0f, dot));
                const bool valid = inb && (d2 < R2);
                const unsigned mask = __ballot_sync(0xffffffffu, valid);
                if (valid) {
                    const int pos = cnt + __popc(mask & ((1u << lane) - 1u));
                    if (pos < CAP) buf[w][pos] = __float_as_int(q.w);
                }
                cnt += __popc(mask);
            }
        }
    }
    __syncwarp();

    // Rank-select 32 smallest indices (unique values -> ranks unique)
    const int cc = cnt < CAP ? cnt : CAP;
    const int IMAX = 0x7fffffff;
    const int v0 = (lane      < cc) ? buf[w][lane]      : IMAX;
    const int v1 = (lane + 32 < cc) ? buf[w][lane + 32] : IMAX;
    const int v2 = (lane + 64 < cc) ? buf[w][lane + 64] : IMAX;
    const int v3 = (lane + 96 < cc) ? buf[w][lane + 96] : IMAX;
    int r0 = 0, r1 = 0, r2 = 0, r3 = 0;
    for (int g = 0; g < cc; ++g) {
        const int u = buf[w][g];                  // broadcast read
        r0 += (u < v0); r1 += (u < v1); r2 += (u < v2); r3 += (u < v3);
    }
    if (lane      < cc && r0 < KK) sidx[w][r0] = v0;
    if (lane + 32 < cc && r1 < KK) sidx[w][r1] = v1;
    if (lane + 64 < cc && r2 < KK) sidx[w][r2] = v2;
    if (lane + 96 < cc && r3 < KK) sidx[w][r3] = v3;
    // astronomically-rare overflow of the 128-reg path (cc in (128,256])
    for (int j = 128 + lane; j < cc; j += 32) {
        const int v = buf[w][j];
        int r = 0;
        for (int g = 0; g < cc; ++g) r += (buf[w][g] < v);
        if (r < KK) sidx[w][r] = v;
    }
    __syncwarp();

    int outv;
    if (cnt == 0) {
        outv = 0;
    } else {
        const int first = sidx[w][0];
        outv = (lane < cnt) ? sidx[w][lane] : first;
    }
    g_idx[(b * MM + m) * KK + lane] = outv;
}

// ---------------------------------------------------------------------------
// Transpose features [B][C][N] -> [B][N][C]
// ---------------------------------------------------------------------------
__global__ __launch_bounds__(256) void transpose_feat_kernel(
    const float* __restrict__ feat)
{
    __shared__ float sm[32][33];
    const int n0 = blockIdx.x * 32;
    const int b  = blockIdx.y;
    const int tx = threadIdx.x;
    const int ty = threadIdx.y;

    #pragma unroll
    for (int i = ty; i < 32; i += 8)
        sm[i][tx] = feat[(b * CC + i) * NN + n0 + tx];
    __syncthreads();
    #pragma unroll
    for (int i = ty; i < 32; i += 8)
        g_feat_t[(size_t)(b * NN + n0 + i) * CC + tx] = sm[tx][i];
}

// ---------------------------------------------------------------------------
// Coords grouping: grid (M/128, 6, B); y encodes c (0..2) x k-half (0..1).
// ---------------------------------------------------------------------------
__global__ __launch_bounds__(128) void group_coords_kernel(
    const float* __restrict__ pts,
    const float* __restrict__ ctr,
    float* __restrict__ out)
{
    __shared__ int sidx[128 * 17];

    const int tid = threadIdx.x;
    const int m0 = blockIdx.x * 128;
    const int c  = blockIdx.y >> 1;
    const int k0 = (blockIdx.y & 1) * 16;
    const int b  = blockIdx.z;

    const int* __restrict__ gbase = g_idx + (b * MM + m0) * KK;
    #pragma unroll
    for (int t = tid; t < 128 * 16; t += 128) {
        const int ml = t >> 4, k = t & 15;
        sidx[ml * 17 + k] = gbase[ml * KK + k0 + k];
    }
    __syncthreads();

    const float* __restrict__ src = pts + (b * 3 + c) * NN;
    const float sub = ctr[(b * 3 + c) * MM + m0 + tid];
    float* __restrict__ o = out + (size_t)((b * 35 + c) * KK + k0) * MM + m0 + tid;
    const int* __restrict__ myidx = &sidx[tid * 17];

    float vals[16];
    #pragma unroll
    for (int k = 0; k < 16; ++k) vals[k] = __ldg(src + myidx[k]);
    #pragma unroll
    for (int k = 0; k < 16; ++k) o[(size_t)k * MM] = __fadd_rn(vals[k], -sub);
}

// ---------------------------------------------------------------------------
// Feature grouping: grid (M/32, 4, B) = 1024 blocks, 256 thr (8 warps).
// Block handles m-tile 32, k-range kc*8..kc*8+7, all 32 channels.
// Warp w owns k = kc*8+w; per m: one coalesced 128B row gather (lane=channel),
// staged into padded smem, then coalesced-over-m stores.
// ---------------------------------------------------------------------------
__global__ __launch_bounds__(256) void group_feat_kernel(
    float* __restrict__ out)
{
    __shared__ int   sidx2[32 * 8];          // [m][kk]
    __shared__ float tile[32 * 257];         // [c][w*32+m], padded

    const int tid  = threadIdx.x;
    const int w    = tid >> 5;
    const int lane = tid & 31;
    const int m0 = blockIdx.x * 32;
    const int kc = blockIdx.y;
    const int b  = blockIdx.z;

    // load this block's 32x8 index slab
    {
        const int ml = tid >> 3, kk = tid & 7;
        sidx2[ml * 8 + kk] = g_idx[(b * MM + m0 + ml) * KK + kc * 8 + kk];
    }
    __syncthreads();

    const float* __restrict__ ft = g_feat_t + (size_t)b * NN * CC;

    #pragma unroll
    for (int m = 0; m < 32; ++m) {
        const int idx = sidx2[m * 8 + w];                    // broadcast
        tile[lane * 257 + w * 32 + m] = __ldg(ft + (size_t)idx * CC + lane);
    }
    __syncthreads();

    #pragma unroll
    for (int i = 0; i < 32; ++i) {
        out[(size_t)((b * 35 + 3 + i) * KK + kc * 8 + w) * MM + m0 + lane] =
            tile[i * 257 + w * 32 + lane];
    }
}

extern "C" void kernel_launch(void* const* d_in, const int* in_sizes, int n_in,
                              void* d_out, int out_size)
{
    const float* pts  = (const float*)d_in[0];   // [B][3][N]
    const float* ctr  = (const float*)d_in[1];   // [B][3][M]
    const float* feat = (const float*)d_in[2];   // [B][C][N]
    float* out = (float*)d_out;

    zero_cells_kernel<<<(BB * NCELL + 255) / 256, 256>>>();
    count_kernel<<<(BB * NN + 255) / 256, 256>>>(pts);
    prefix_kernel<<<BB, 1024>>>();
    scatter_kernel<<<(BB * NN + 255) / 256, 256>>>(pts);
    query_kernel<<<BB * MM / QW, 256>>>(ctr);

    {
        dim3 grid(NN / 32, BB);
        dim3 block(32, 8);
        transpose_feat_kernel<<<grid, block>>>(feat);
    }
    {
        dim3 grid(MM / 128, 6, BB);
        group_coords_kernel<<<grid, 128>>>(pts, ctr, out);
    }
    {
        dim3 grid(MM / 32, 4, BB);
        group_feat_kernel<<<grid, 256>>>(out);
    }
}